// round 2
// baseline (speedup 1.0000x reference)
#include <cuda_runtime.h>
#include <math.h>

#define B_  4
#define S_  2048
#define HID_ 1280
#define NH_ 16
#define NKV_ 4
#define HD_ 80
#define QKV_DIM_ 1920
#define M_TOT_ (B_ * S_)   // 8192
#define GQA_G_ (NH_ / NKV_)

// ---------------- scratch (static device memory; no allocation) ----------------
__device__ float g_q[(size_t)B_ * NH_ * S_ * HD_];    // [B*NH, S, HD] scaled queries
__device__ float g_k[(size_t)B_ * NKV_ * S_ * HD_];   // [B*NKV, S, HD]
__device__ float g_v[(size_t)B_ * NKV_ * S_ * HD_];   // [B*NKV, S, HD]
__device__ float g_o[(size_t)B_ * S_ * HID_];         // [B*S, NH*HD] attention output
__device__ float g_qscale[HD_];

// ---------------- qscale = r_softplus_0/sqrt(HD) * softplus(scaling) ----------------
__global__ void qscale_kernel(const float* __restrict__ scaling) {
    int d = threadIdx.x;
    if (d < HD_) {
        float x = scaling[d];
        float sp = log1pf(expf(x));
        g_qscale[d] = 1.442695041f * rsqrtf((float)HD_) * sp;
    }
}

// ---------------- tiled fp32 GEMM: C[m,n] = sum_k A[m,k] * W[n,k] + bias[n] ----------------
// BM=BN=128, BK=16, 256 threads, 8x8 microtile.
// MODE 0: A = harness hidden_states (argument); epilogue scatters into g_q/g_k/g_v.
// MODE 1: A = g_o (device global, referenced in DEVICE code); epilogue writes dense C.
template <int MODE>
__global__ __launch_bounds__(256) void gemm_kernel(
    const float* __restrict__ A_arg, // MODE 0: [M, K] input; MODE 1: ignored
    const float* __restrict__ W,     // [N, K]
    const float* __restrict__ bias,  // [N]
    float* __restrict__ C,           // MODE 1 only: [M, N]
    int N, int K)
{
    // IMPORTANT: device-side reference to the __device__ global (valid address).
    const float* A = (MODE == 1) ? (const float*)g_o : A_arg;

    const int BM = 128, BN = 128, BK = 16;
    __shared__ float As[BK][BM];  // transposed: As[k][m]
    __shared__ float Bs[BK][BN];  // transposed: Bs[k][n]

    int tid = threadIdx.x;
    int tx = tid & 15;        // 0..15 -> n
    int ty = tid >> 4;        // 0..15 -> m
    int bm = blockIdx.y * BM;
    int bn = blockIdx.x * BN;

    float acc[8][8];
#pragma unroll
    for (int i = 0; i < 8; i++)
#pragma unroll
        for (int j = 0; j < 8; j++) acc[i][j] = 0.0f;

    for (int k0 = 0; k0 < K; k0 += BK) {
        // load tiles: 128x16 each = 512 float4; 2 per thread per matrix
#pragma unroll
        for (int it = 0; it < 2; it++) {
            int idx = tid + it * 256;
            int r  = idx >> 2;          // 0..127
            int c4 = (idx & 3) * 4;     // 0,4,8,12
            float4 va = *(const float4*)&A[(size_t)(bm + r) * K + k0 + c4];
            As[c4 + 0][r] = va.x; As[c4 + 1][r] = va.y;
            As[c4 + 2][r] = va.z; As[c4 + 3][r] = va.w;
            float4 vb = *(const float4*)&W[(size_t)(bn + r) * K + k0 + c4];
            Bs[c4 + 0][r] = vb.x; Bs[c4 + 1][r] = vb.y;
            Bs[c4 + 2][r] = vb.z; Bs[c4 + 3][r] = vb.w;
        }
        __syncthreads();

#pragma unroll
        for (int kk = 0; kk < BK; kk++) {
            float4 a0 = *(const float4*)&As[kk][ty * 8];
            float4 a1 = *(const float4*)&As[kk][ty * 8 + 4];
            float4 b0 = *(const float4*)&Bs[kk][tx * 8];
            float4 b1 = *(const float4*)&Bs[kk][tx * 8 + 4];
            float a[8] = {a0.x, a0.y, a0.z, a0.w, a1.x, a1.y, a1.z, a1.w};
            float b[8] = {b0.x, b0.y, b0.z, b0.w, b1.x, b1.y, b1.z, b1.w};
#pragma unroll
            for (int i = 0; i < 8; i++)
#pragma unroll
                for (int j = 0; j < 8; j++) acc[i][j] += a[i] * b[j];
        }
        __syncthreads();
    }

    // epilogue
#pragma unroll
    for (int i = 0; i < 8; i++) {
        int row = bm + ty * 8 + i;
#pragma unroll
        for (int j = 0; j < 8; j++) {
            int col = bn + tx * 8 + j;
            float val = acc[i][j] + bias[col];
            if (MODE == 0) {
                int b = row / S_, s = row % S_;
                if (col < NH_ * HD_) {
                    int h = col / HD_, d = col % HD_;
                    g_q[(((size_t)(b * NH_ + h)) * S_ + s) * HD_ + d] = val * g_qscale[d];
                } else if (col < NH_ * HD_ + NKV_ * HD_) {
                    int cc = col - NH_ * HD_;
                    int h = cc / HD_, d = cc % HD_;
                    g_k[(((size_t)(b * NKV_ + h)) * S_ + s) * HD_ + d] = val;
                } else {
                    int cc = col - NH_ * HD_ - NKV_ * HD_;
                    int h = cc / HD_, d = cc % HD_;
                    g_v[(((size_t)(b * NKV_ + h)) * S_ + s) * HD_ + d] = val;
                }
            } else {
                C[(size_t)row * N + col] = val;
            }
        }
    }
}

// ---------------- causal flash attention, BR=BC=64, fp32 ----------------
#define BR_ 64
#define BC_ 64

struct AttnSmem {
    float Qs[BR_][HD_ + 4];   // [row][d]
    float Kt[HD_][BC_ + 4];   // [d][col]
    float Vs[BC_][HD_ + 4];   // [k][d]
    float Ps[BR_][BC_ + 4];   // [row][k]
};

__global__ __launch_bounds__(256) void attn_kernel() {
    extern __shared__ char smem_raw[];
    AttnSmem& sm = *reinterpret_cast<AttnSmem*>(smem_raw);

    int tid = threadIdx.x;
    int tx = tid & 15;   // cols
    int ty = tid >> 4;   // rows
    int qt = blockIdx.x;            // q tile index (0..31)
    int bh = blockIdx.y;            // b*NH + h
    int b = bh / NH_, h = bh % NH_;
    int kvh = h / GQA_G_;
    int q0 = qt * BR_;

    const float* qptr = g_q + ((size_t)bh * S_ + q0) * HD_;
    const float* kbase = g_k + ((size_t)(b * NKV_ + kvh)) * S_ * HD_;
    const float* vbase = g_v + ((size_t)(b * NKV_ + kvh)) * S_ * HD_;

    // load Q tile
    for (int i = tid; i < BR_ * (HD_ / 4); i += 256) {
        int r = i / (HD_ / 4);
        int c4 = (i % (HD_ / 4)) * 4;
        *(float4*)&sm.Qs[r][c4] = *(const float4*)&qptr[(size_t)r * HD_ + c4];
    }

    float m[4], l[4], acc[4][5];
#pragma unroll
    for (int r = 0; r < 4; r++) {
        m[r] = -3.0e38f;
        l[r] = 0.0f;
#pragma unroll
        for (int c = 0; c < 5; c++) acc[r][c] = 0.0f;
    }

    for (int kt = 0; kt <= qt; kt++) {
        int k0 = kt * BC_;
        __syncthreads();  // previous iter's Ps/Vs consumers done (also covers Q load, iter 0)

        const float* kp = kbase + (size_t)k0 * HD_;
        const float* vp = vbase + (size_t)k0 * HD_;
        for (int i = tid; i < BC_ * (HD_ / 4); i += 256) {
            int r = i / (HD_ / 4);
            int c4 = (i % (HD_ / 4)) * 4;
            float4 kv = *(const float4*)&kp[(size_t)r * HD_ + c4];
            sm.Kt[c4 + 0][r] = kv.x; sm.Kt[c4 + 1][r] = kv.y;
            sm.Kt[c4 + 2][r] = kv.z; sm.Kt[c4 + 3][r] = kv.w;
            *(float4*)&sm.Vs[r][c4] = *(const float4*)&vp[(size_t)r * HD_ + c4];
        }
        __syncthreads();

        // S = Q K^T for this thread's 4x4 sub-tile
        float s[4][4];
#pragma unroll
        for (int r = 0; r < 4; r++)
#pragma unroll
            for (int c = 0; c < 4; c++) s[r][c] = 0.0f;

#pragma unroll 4
        for (int d = 0; d < HD_; d++) {
            float4 kv = *(const float4*)&sm.Kt[d][tx * 4];
#pragma unroll
            for (int r = 0; r < 4; r++) {
                float qv = sm.Qs[ty * 4 + r][d];
                s[r][0] += qv * kv.x;
                s[r][1] += qv * kv.y;
                s[r][2] += qv * kv.z;
                s[r][3] += qv * kv.w;
            }
        }

        // causal mask on diagonal tile
        if (kt == qt) {
#pragma unroll
            for (int r = 0; r < 4; r++) {
                int qrow = q0 + ty * 4 + r;
#pragma unroll
                for (int c = 0; c < 4; c++) {
                    int kcol = k0 + tx * 4 + c;
                    if (kcol > qrow) s[r][c] = -3.0e38f;
                }
            }
        }

        // online softmax update (row reduction across the 16 tx lanes)
#pragma unroll
        for (int r = 0; r < 4; r++) {
            float mloc = fmaxf(fmaxf(s[r][0], s[r][1]), fmaxf(s[r][2], s[r][3]));
#pragma unroll
            for (int off = 8; off > 0; off >>= 1)
                mloc = fmaxf(mloc, __shfl_xor_sync(0xffffffffu, mloc, off));
            float mnew = fmaxf(m[r], mloc);
            float alpha = __expf(m[r] - mnew);
            float psum = 0.0f;
#pragma unroll
            for (int c = 0; c < 4; c++) {
                float p = __expf(s[r][c] - mnew);
                s[r][c] = p;
                psum += p;
            }
#pragma unroll
            for (int off = 8; off > 0; off >>= 1)
                psum += __shfl_xor_sync(0xffffffffu, psum, off);
            l[r] = l[r] * alpha + psum;
            m[r] = mnew;
#pragma unroll
            for (int c = 0; c < 5; c++) acc[r][c] *= alpha;
#pragma unroll
            for (int c = 0; c < 4; c++) sm.Ps[ty * 4 + r][tx * 4 + c] = s[r][c];
        }
        __syncthreads();

        // acc += P @ V  (this thread: rows ty*4.., cols tx*5..)
#pragma unroll 4
        for (int kk = 0; kk < BC_; kk++) {
            float pr[4];
#pragma unroll
            for (int r = 0; r < 4; r++) pr[r] = sm.Ps[ty * 4 + r][kk];
            float vv[5];
#pragma unroll
            for (int c = 0; c < 5; c++) vv[c] = sm.Vs[kk][tx * 5 + c];
#pragma unroll
            for (int r = 0; r < 4; r++)
#pragma unroll
                for (int c = 0; c < 5; c++) acc[r][c] += pr[r] * vv[c];
        }
    }

    // write out: g_o[(b*S + qrow), h*HD + col]
#pragma unroll
    for (int r = 0; r < 4; r++) {
        float inv = 1.0f / l[r];
        int qrow = q0 + ty * 4 + r;
        float* op = g_o + ((size_t)(b * S_) + qrow) * HID_ + h * HD_ + tx * 5;
#pragma unroll
        for (int c = 0; c < 5; c++) op[c] = acc[r][c] * inv;
    }
}

// ---------------- launch ----------------
extern "C" void kernel_launch(void* const* d_in, const int* in_sizes, int n_in,
                              void* d_out, int out_size) {
    const float* hs      = (const float*)d_in[0];
    // d_in[1] = mask: known causal, not needed
    const float* scaling = (const float*)d_in[2];
    const float* qkv_w   = (const float*)d_in[3];
    const float* qkv_b   = (const float*)d_in[4];
    const float* o_w     = (const float*)d_in[5];
    const float* o_b     = (const float*)d_in[6];
    float* out = (float*)d_out;

    const int attn_smem = (int)sizeof(AttnSmem);
    static bool attr_set = false;
    if (!attr_set) {
        cudaFuncSetAttribute(attn_kernel, cudaFuncAttributeMaxDynamicSharedMemorySize, attn_smem);
        attr_set = true;
    }

    qscale_kernel<<<1, 128>>>(scaling);

    dim3 g1(QKV_DIM_ / 128, M_TOT_ / 128);
    gemm_kernel<0><<<g1, 256>>>(hs, qkv_w, qkv_b, nullptr, QKV_DIM_, HID_);

    dim3 ga(S_ / BR_, B_ * NH_);
    attn_kernel<<<ga, 256, attn_smem>>>();

    dim3 g3(HID_ / 128, M_TOT_ / 128);
    gemm_kernel<1><<<g3, 256>>>(nullptr, o_w, o_b, out, HID_, HID_);
}

// round 4
// speedup vs baseline: 1.1749x; 1.1749x over previous
#include <cuda_runtime.h>
#include <math.h>
#include <stdint.h>

#define B_  4
#define S_  2048
#define HID_ 1280
#define NH_ 16
#define NKV_ 4
#define HD_ 80
#define QKV_DIM_ 1920
#define M_TOT_ (B_ * S_)   // 8192
#define GQA_G_ (NH_ / NKV_)

// ---------------- scratch ----------------
__device__ float g_q[(size_t)B_ * NH_ * S_ * HD_];    // [B*NH, S, HD] scaled queries
__device__ float g_k[(size_t)B_ * NKV_ * S_ * HD_];   // [B*NKV, S, HD]
__device__ float g_v[(size_t)B_ * NKV_ * S_ * HD_];   // [B*NKV, S, HD]
__device__ float g_o[(size_t)B_ * S_ * HID_];         // [B*S, NH*HD] attention output
__device__ float g_qscale[HD_];

// tf32 helpers: 3xTF32 error-compensated path
__device__ __forceinline__ uint32_t tf32_of(float x) {
    uint32_t u;
    asm("cvt.rna.tf32.f32 %0, %1;" : "=r"(u) : "f"(x));
    return u;
}
__device__ __forceinline__ void tf32_split(float x, uint32_t& hi, uint32_t& lo) {
    hi = tf32_of(x);
    lo = tf32_of(x - __uint_as_float(hi));
}

// tf32 m16n8k8 mma: D = A(16x8 row) * B(8x8 col) + D, fp32 accum
__device__ __forceinline__ void mma_tf32(float* c, const uint32_t* a, const uint32_t* b) {
    asm volatile(
        "mma.sync.aligned.m16n8k8.row.col.f32.tf32.tf32.f32 "
        "{%0,%1,%2,%3}, {%4,%5,%6,%7}, {%8,%9}, {%0,%1,%2,%3};\n"
        : "+f"(c[0]), "+f"(c[1]), "+f"(c[2]), "+f"(c[3])
        : "r"(a[0]), "r"(a[1]), "r"(a[2]), "r"(a[3]), "r"(b[0]), "r"(b[1]));
}
// 3xTF32: c += alo*bhi + ahi*blo + ahi*bhi (small terms first)
__device__ __forceinline__ void mma3(float* c, const uint32_t* ah, const uint32_t* al,
                                     const uint32_t* bh, const uint32_t* bl) {
    mma_tf32(c, al, bh);
    mma_tf32(c, ah, bl);
    mma_tf32(c, ah, bh);
}

// ---------------- qscale ----------------
__global__ void qscale_kernel(const float* __restrict__ scaling) {
    int d = threadIdx.x;
    if (d < HD_) {
        float x = scaling[d];
        float sp = log1pf(expf(x));
        g_qscale[d] = 1.442695041f * rsqrtf((float)HD_) * sp;
    }
}

// ---------------- tensor-core GEMM: C[m,n] = sum_k A[m,k] * W[n,k] + bias[n] ------
// BM=BN=128, BK=16, 256 threads = 8 warps, warp tile 64x32 (wm 0..1, wn 0..3).
#define GLDS 136   // smem row stride (conflict-free fragment access)

template <int MODE>
__global__ __launch_bounds__(256) void gemm_tc(
    const float* __restrict__ A_arg, const float* __restrict__ W,
    const float* __restrict__ bias, float* __restrict__ C, int N, int K)
{
    const float* A = (MODE == 1) ? (const float*)g_o : A_arg;

    __shared__ float As[16][GLDS];   // [k][m]
    __shared__ float Bs[16][GLDS];   // [k][n]

    int tid = threadIdx.x;
    int lane = tid & 31, wid = tid >> 5;
    int g = lane >> 2, tig = lane & 3;
    int wm = wid >> 2, wn = wid & 3;      // wm: 0..1 (64 rows), wn: 0..3 (32 cols)
    int bm = blockIdx.y * 128, bn = blockIdx.x * 128;

    float acc[4][4][4];
#pragma unroll
    for (int mi = 0; mi < 4; mi++)
#pragma unroll
        for (int ni = 0; ni < 4; ni++)
#pragma unroll
            for (int c = 0; c < 4; c++) acc[mi][ni][c] = 0.0f;

    int r0 = tid >> 2;            // 0..63 (rows r0 and r0+64)
    int c4 = (tid & 3) * 4;       // 0,4,8,12

    float4 pa[2], pb[2];
    {
        const float* Ap = A + (size_t)bm * K;
        const float* Wp = W + (size_t)bn * K;
        pa[0] = *(const float4*)&Ap[(size_t)r0 * K + c4];
        pa[1] = *(const float4*)&Ap[(size_t)(r0 + 64) * K + c4];
        pb[0] = *(const float4*)&Wp[(size_t)r0 * K + c4];
        pb[1] = *(const float4*)&Wp[(size_t)(r0 + 64) * K + c4];
    }

    for (int k0 = 0; k0 < K; k0 += 16) {
#pragma unroll
        for (int i = 0; i < 2; i++) {
            int rr = r0 + i * 64;
            As[c4 + 0][rr] = pa[i].x; As[c4 + 1][rr] = pa[i].y;
            As[c4 + 2][rr] = pa[i].z; As[c4 + 3][rr] = pa[i].w;
            Bs[c4 + 0][rr] = pb[i].x; Bs[c4 + 1][rr] = pb[i].y;
            Bs[c4 + 2][rr] = pb[i].z; Bs[c4 + 3][rr] = pb[i].w;
        }
        __syncthreads();

        if (k0 + 16 < K) {
            const float* Ap = A + (size_t)bm * K + (k0 + 16);
            const float* Wp = W + (size_t)bn * K + (k0 + 16);
            pa[0] = *(const float4*)&Ap[(size_t)r0 * K + c4];
            pa[1] = *(const float4*)&Ap[(size_t)(r0 + 64) * K + c4];
            pb[0] = *(const float4*)&Wp[(size_t)r0 * K + c4];
            pb[1] = *(const float4*)&Wp[(size_t)(r0 + 64) * K + c4];
        }

#pragma unroll
        for (int ks = 0; ks < 2; ks++) {
            int kk = ks * 8;
            uint32_t afh[4][4], afl[4][4], bfh[4][2], bfl[4][2];
#pragma unroll
            for (int mi = 0; mi < 4; mi++) {
                int m0 = wm * 64 + mi * 16;
                tf32_split(As[kk + tig][m0 + g],          afh[mi][0], afl[mi][0]);
                tf32_split(As[kk + tig][m0 + g + 8],      afh[mi][1], afl[mi][1]);
                tf32_split(As[kk + tig + 4][m0 + g],      afh[mi][2], afl[mi][2]);
                tf32_split(As[kk + tig + 4][m0 + g + 8],  afh[mi][3], afl[mi][3]);
            }
#pragma unroll
            for (int ni = 0; ni < 4; ni++) {
                int n0 = wn * 32 + ni * 8;
                tf32_split(Bs[kk + tig][n0 + g],     bfh[ni][0], bfl[ni][0]);
                tf32_split(Bs[kk + tig + 4][n0 + g], bfh[ni][1], bfl[ni][1]);
            }
#pragma unroll
            for (int mi = 0; mi < 4; mi++)
#pragma unroll
                for (int ni = 0; ni < 4; ni++)
                    mma3(acc[mi][ni], afh[mi], afl[mi], bfh[ni], bfl[ni]);
        }
        __syncthreads();
    }

    // epilogue
#pragma unroll
    for (int mi = 0; mi < 4; mi++) {
#pragma unroll
        for (int ni = 0; ni < 4; ni++) {
#pragma unroll
            for (int c = 0; c < 4; c++) {
                int row = bm + wm * 64 + mi * 16 + g + (c >= 2 ? 8 : 0);
                int col = bn + wn * 32 + ni * 8 + tig * 2 + (c & 1);
                float val = acc[mi][ni][c] + bias[col];
                if (MODE == 0) {
                    int b = row / S_, s = row % S_;
                    if (col < NH_ * HD_) {
                        int h = col / HD_, d = col % HD_;
                        g_q[(((size_t)(b * NH_ + h)) * S_ + s) * HD_ + d] = val * g_qscale[d];
                    } else if (col < NH_ * HD_ + NKV_ * HD_) {
                        int cc = col - NH_ * HD_;
                        int h = cc / HD_, d = cc % HD_;
                        g_k[(((size_t)(b * NKV_ + h)) * S_ + s) * HD_ + d] = val;
                    } else {
                        int cc = col - NH_ * HD_ - NKV_ * HD_;
                        int h = cc / HD_, d = cc % HD_;
                        g_v[(((size_t)(b * NKV_ + h)) * S_ + s) * HD_ + d] = val;
                    }
                } else {
                    C[(size_t)row * N + col] = val;
                }
            }
        }
    }
}

// ---------------- causal flash attention w/ 3xTF32 MMA, BR=BC=64 ----------------
#define BR_ 64
#define BC_ 64

struct AttnSmem {
    float Qs[BR_][84];        // [row][d]
    float Kt[HD_][72];        // [d][kcol]
    float Vs[BC_][88];        // [k][d]
    float Ps[BR_][68];        // S then P
    float row_scale[BR_];     // alpha / linv broadcast
};

__global__ __launch_bounds__(256) void attn_kernel() {
    extern __shared__ char smem_raw[];
    AttnSmem& sm = *reinterpret_cast<AttnSmem*>(smem_raw);

    int tid = threadIdx.x;
    int lane = tid & 31, wid = tid >> 5;
    int g = lane >> 2, tig = lane & 3;
    int wm = wid >> 1, wn = wid & 1;   // wm 0..3 (16 rows each), wn 0..1
    int qt = blockIdx.x, bh = blockIdx.y;
    int b = bh / NH_, h = bh % NH_;
    int kvh = h / GQA_G_;
    int q0 = qt * BR_;

    const float* qptr  = g_q + ((size_t)bh * S_ + q0) * HD_;
    const float* kbase = g_k + ((size_t)(b * NKV_ + kvh)) * S_ * HD_;
    const float* vbase = g_v + ((size_t)(b * NKV_ + kvh)) * S_ * HD_;

    // load Q tile
    for (int i = tid; i < BR_ * (HD_ / 4); i += 256) {
        int r = i / (HD_ / 4);
        int cc = (i % (HD_ / 4)) * 4;
        *(float4*)&sm.Qs[r][cc] = *(const float4*)&qptr[(size_t)r * HD_ + cc];
    }

    float accO[5][4];
#pragma unroll
    for (int ni = 0; ni < 5; ni++)
#pragma unroll
        for (int c = 0; c < 4; c++) accO[ni][c] = 0.0f;

    int srow = tid >> 2, quad = tid & 3;
    int qrow = q0 + srow;
    float mrow = -3.0e38f, lrow = 0.0f;

    for (int kt = 0; kt <= qt; kt++) {
        int k0 = kt * BC_;
        __syncthreads();

        const float* kp = kbase + (size_t)k0 * HD_;
        const float* vp = vbase + (size_t)k0 * HD_;
        for (int i = tid; i < BC_ * (HD_ / 4); i += 256) {
            int r = i / (HD_ / 4);
            int cc = (i % (HD_ / 4)) * 4;
            float4 kv = *(const float4*)&kp[(size_t)r * HD_ + cc];
            sm.Kt[cc + 0][r] = kv.x; sm.Kt[cc + 1][r] = kv.y;
            sm.Kt[cc + 2][r] = kv.z; sm.Kt[cc + 3][r] = kv.w;
            *(float4*)&sm.Vs[r][cc] = *(const float4*)&vp[(size_t)r * HD_ + cc];
        }
        __syncthreads();

        // ---- S = Q K^T via 3xTF32 MMA; warp tile 16x32 at (wm*16, wn*32) ----
        float sfrag[4][4];
#pragma unroll
        for (int ni = 0; ni < 4; ni++)
#pragma unroll
            for (int c = 0; c < 4; c++) sfrag[ni][c] = 0.0f;

#pragma unroll
        for (int ks = 0; ks < 10; ks++) {
            int kk = ks * 8;
            uint32_t ah[4], al[4];
            tf32_split(sm.Qs[wm * 16 + g][kk + tig],         ah[0], al[0]);
            tf32_split(sm.Qs[wm * 16 + g + 8][kk + tig],     ah[1], al[1]);
            tf32_split(sm.Qs[wm * 16 + g][kk + tig + 4],     ah[2], al[2]);
            tf32_split(sm.Qs[wm * 16 + g + 8][kk + tig + 4], ah[3], al[3]);
#pragma unroll
            for (int ni = 0; ni < 4; ni++) {
                int n0 = wn * 32 + ni * 8;
                uint32_t bh2[2], bl2[2];
                tf32_split(sm.Kt[kk + tig][n0 + g],     bh2[0], bl2[0]);
                tf32_split(sm.Kt[kk + tig + 4][n0 + g], bh2[1], bl2[1]);
                mma3(sfrag[ni], ah, al, bh2, bl2);
            }
        }
        // store S
#pragma unroll
        for (int ni = 0; ni < 4; ni++) {
            int n0 = wn * 32 + ni * 8 + tig * 2;
            sm.Ps[wm * 16 + g][n0]     = sfrag[ni][0];
            sm.Ps[wm * 16 + g][n0 + 1] = sfrag[ni][1];
            sm.Ps[wm * 16 + g + 8][n0]     = sfrag[ni][2];
            sm.Ps[wm * 16 + g + 8][n0 + 1] = sfrag[ni][3];
        }
        __syncthreads();

        // ---- online softmax (SIMT): 4 threads per row ----
        {
            float sv[16];
            float mx = -3.0e38f;
            bool diag = (kt == qt);
#pragma unroll
            for (int c = 0; c < 16; c++) {
                int col = quad * 16 + c;
                float x = sm.Ps[srow][col];
                if (diag && (k0 + col) > qrow) x = -3.0e38f;
                sv[c] = x;
                mx = fmaxf(mx, x);
            }
            mx = fmaxf(mx, __shfl_xor_sync(0xffffffffu, mx, 1));
            mx = fmaxf(mx, __shfl_xor_sync(0xffffffffu, mx, 2));
            float mnew = fmaxf(mrow, mx);
            float alpha = __expf(mrow - mnew);
            float psum = 0.0f;
#pragma unroll
            for (int c = 0; c < 16; c++) {
                float p = __expf(sv[c] - mnew);
                sm.Ps[srow][quad * 16 + c] = p;
                psum += p;
            }
            psum += __shfl_xor_sync(0xffffffffu, psum, 1);
            psum += __shfl_xor_sync(0xffffffffu, psum, 2);
            lrow = lrow * alpha + psum;
            mrow = mnew;
            if (quad == 0) sm.row_scale[srow] = alpha;
        }
        __syncthreads();

        // ---- rescale + O += P V via 3xTF32 MMA; warp tile 16x40 at (wm*16, wn*40) ----
        {
            float al0 = sm.row_scale[wm * 16 + g];
            float al1 = sm.row_scale[wm * 16 + g + 8];
#pragma unroll
            for (int ni = 0; ni < 5; ni++) {
                accO[ni][0] *= al0; accO[ni][1] *= al0;
                accO[ni][2] *= al1; accO[ni][3] *= al1;
            }
#pragma unroll
            for (int ks = 0; ks < 8; ks++) {
                int kk = ks * 8;
                uint32_t ah[4], al[4];
                tf32_split(sm.Ps[wm * 16 + g][kk + tig],         ah[0], al[0]);
                tf32_split(sm.Ps[wm * 16 + g + 8][kk + tig],     ah[1], al[1]);
                tf32_split(sm.Ps[wm * 16 + g][kk + tig + 4],     ah[2], al[2]);
                tf32_split(sm.Ps[wm * 16 + g + 8][kk + tig + 4], ah[3], al[3]);
#pragma unroll
                for (int ni = 0; ni < 5; ni++) {
                    int n0 = wn * 40 + ni * 8;
                    uint32_t bh2[2], bl2[2];
                    tf32_split(sm.Vs[kk + tig][n0 + g],     bh2[0], bl2[0]);
                    tf32_split(sm.Vs[kk + tig + 4][n0 + g], bh2[1], bl2[1]);
                    mma3(accO[ni], ah, al, bh2, bl2);
                }
            }
        }
    }

    // final normalization
    __syncthreads();
    if (quad == 0) sm.row_scale[srow] = 1.0f / lrow;
    __syncthreads();
    float l0 = sm.row_scale[wm * 16 + g];
    float l1 = sm.row_scale[wm * 16 + g + 8];
#pragma unroll
    for (int ni = 0; ni < 5; ni++) {
        int cout = wn * 40 + ni * 8 + tig * 2;
        int rr0 = q0 + wm * 16 + g;
        int rr1 = rr0 + 8;
        float* o0 = g_o + ((size_t)(b * S_) + rr0) * HID_ + h * HD_ + cout;
        float* o1 = g_o + ((size_t)(b * S_) + rr1) * HID_ + h * HD_ + cout;
        o0[0] = accO[ni][0] * l0; o0[1] = accO[ni][1] * l0;
        o1[0] = accO[ni][2] * l1; o1[1] = accO[ni][3] * l1;
    }
}

// ---------------- launch ----------------
extern "C" void kernel_launch(void* const* d_in, const int* in_sizes, int n_in,
                              void* d_out, int out_size) {
    const float* hs      = (const float*)d_in[0];
    const float* scaling = (const float*)d_in[2];
    const float* qkv_w   = (const float*)d_in[3];
    const float* qkv_b   = (const float*)d_in[4];
    const float* o_w     = (const float*)d_in[5];
    const float* o_b     = (const float*)d_in[6];
    float* out = (float*)d_out;

    const int attn_smem = (int)sizeof(AttnSmem);
    cudaFuncSetAttribute(attn_kernel, cudaFuncAttributeMaxDynamicSharedMemorySize, attn_smem);

    qscale_kernel<<<1, 128>>>(scaling);

    dim3 g1(QKV_DIM_ / 128, M_TOT_ / 128);
    gemm_tc<0><<<g1, 256>>>(hs, qkv_w, qkv_b, nullptr, QKV_DIM_, HID_);

    dim3 ga(S_ / BR_, B_ * NH_);
    attn_kernel<<<ga, 256, attn_smem>>>();

    dim3 g3(HID_ / 128, M_TOT_ / 128);
    gemm_tc<1><<<g3, 256>>>(nullptr, o_w, o_b, out, HID_, HID_);
}

// round 5
// speedup vs baseline: 1.7726x; 1.5088x over previous
#include <cuda_runtime.h>
#include <cuda_bf16.h>
#include <math.h>
#include <stdint.h>

#define B_  4
#define S_  2048
#define HID_ 1280
#define NH_ 16
#define NKV_ 4
#define HD_ 80
#define QKV_DIM_ 1920
#define M_TOT_ (B_ * S_)   // 8192
#define GQA_G_ (NH_ / NKV_)

// ---------------- scratch ----------------
__device__ float g_q[(size_t)B_ * NH_ * S_ * HD_];    // [B*NH, S, HD] scaled queries
__device__ float g_k[(size_t)B_ * NKV_ * S_ * HD_];   // [B*NKV, S, HD]
__device__ float g_v[(size_t)B_ * NKV_ * S_ * HD_];   // [B*NKV, S, HD]
__device__ float g_o[(size_t)B_ * S_ * HID_];         // [B*S, NH*HD] attention output
__device__ float g_qscale[HD_];

// ---------------- bf16 split helpers ----------------
__device__ __forceinline__ unsigned short bf16b(float x) {
    return __bfloat16_as_ushort(__float2bfloat16_rn(x));
}
// pack two consecutive-K values (x0 = even k -> low half, x1 = odd k -> high half),
// producing hi word and compensation (lo) word.
__device__ __forceinline__ void split_pack(float x0, float x1, uint32_t& hi, uint32_t& lo) {
    unsigned short h0 = bf16b(x0), h1 = bf16b(x1);
    hi = (uint32_t)h0 | ((uint32_t)h1 << 16);
    float f0 = __uint_as_float((uint32_t)h0 << 16);
    float f1 = __uint_as_float((uint32_t)h1 << 16);
    unsigned short l0 = bf16b(x0 - f0), l1 = bf16b(x1 - f1);
    lo = (uint32_t)l0 | ((uint32_t)l1 << 16);
}

// bf16 m16n8k16 mma: D += A(16x16 row) * B(16x8 col), fp32 accum
__device__ __forceinline__ void mma_bf16(float* c, const uint32_t* a, const uint32_t* b) {
    asm volatile(
        "mma.sync.aligned.m16n8k16.row.col.f32.bf16.bf16.f32 "
        "{%0,%1,%2,%3}, {%4,%5,%6,%7}, {%8,%9}, {%0,%1,%2,%3};\n"
        : "+f"(c[0]), "+f"(c[1]), "+f"(c[2]), "+f"(c[3])
        : "r"(a[0]), "r"(a[1]), "r"(a[2]), "r"(a[3]), "r"(b[0]), "r"(b[1]));
}
// 3-term compensated: c += al*bh + ah*bl + ah*bh  (drops lo*lo ~ 2^-18)
__device__ __forceinline__ void mma3(float* c, const uint32_t* ah, const uint32_t* al,
                                     const uint32_t* bh, const uint32_t* bl) {
    mma_bf16(c, al, bh);
    mma_bf16(c, ah, bl);
    mma_bf16(c, ah, bh);
}

// ---------------- qscale ----------------
__global__ void qscale_kernel(const float* __restrict__ scaling) {
    int d = threadIdx.x;
    if (d < HD_) {
        float x = scaling[d];
        float sp = log1pf(expf(x));
        g_qscale[d] = 1.442695041f * rsqrtf((float)HD_) * sp;
    }
}

// ---------------- tensor-core GEMM: C[m,n] = sum_k A[m,k] * W[n,k] + bias[n] ------
// BM=BN=128, BK=32, 256 threads = 8 warps, warp tile 64x32 (wm 0..1, wn 0..3).
// smem holds split-packed bf16x2 tiles: [kpair][m] u32, stride 136 (conflict-free frag reads).
#define GSTR 136

template <int MODE>
__global__ __launch_bounds__(256) void gemm_tc(
    const float* __restrict__ A_arg, const float* __restrict__ W,
    const float* __restrict__ bias, float* __restrict__ C, int N, int K)
{
    const float* A = (MODE == 1) ? (const float*)g_o : A_arg;

    __shared__ uint32_t Ah[16][GSTR], Al[16][GSTR];
    __shared__ uint32_t Bh[16][GSTR], Bl[16][GSTR];

    int tid = threadIdx.x;
    int lane = tid & 31, wid = tid >> 5;
    int g = lane >> 2, tig = lane & 3;
    int wm = wid >> 2, wn = wid & 3;      // wm: 0..1 (64 rows), wn: 0..3 (32 cols)
    int bm = blockIdx.y * 128, bn = blockIdx.x * 128;

    float acc[4][4][4];
#pragma unroll
    for (int mi = 0; mi < 4; mi++)
#pragma unroll
        for (int ni = 0; ni < 4; ni++)
#pragma unroll
            for (int c = 0; c < 4; c++) acc[mi][ni][c] = 0.0f;

    int r0 = tid >> 2;            // 0..63 (rows r0 and r0+64)
    int c4 = (tid & 3) * 4;       // 0,4,8,12 (also +16)

    float4 pa[4], pb[4];
    {
        const float* Ap = A + (size_t)bm * K;
        const float* Wp = W + (size_t)bn * K;
#pragma unroll
        for (int i = 0; i < 2; i++)
#pragma unroll
            for (int j = 0; j < 2; j++) {
                pa[i * 2 + j] = *(const float4*)&Ap[(size_t)(r0 + i * 64) * K + c4 + j * 16];
                pb[i * 2 + j] = *(const float4*)&Wp[(size_t)(r0 + i * 64) * K + c4 + j * 16];
            }
    }

    for (int k0 = 0; k0 < K; k0 += 32) {
        // split+pack prefetched tile into smem
#pragma unroll
        for (int i = 0; i < 2; i++) {
            int rr = r0 + i * 64;
#pragma unroll
            for (int j = 0; j < 2; j++) {
                int kp = (c4 >> 1) + j * 8;
                float4 va = pa[i * 2 + j], vb = pb[i * 2 + j];
                split_pack(va.x, va.y, Ah[kp][rr],     Al[kp][rr]);
                split_pack(va.z, va.w, Ah[kp + 1][rr], Al[kp + 1][rr]);
                split_pack(vb.x, vb.y, Bh[kp][rr],     Bl[kp][rr]);
                split_pack(vb.z, vb.w, Bh[kp + 1][rr], Bl[kp + 1][rr]);
            }
        }
        __syncthreads();

        if (k0 + 32 < K) {
            const float* Ap = A + (size_t)bm * K + (k0 + 32);
            const float* Wp = W + (size_t)bn * K + (k0 + 32);
#pragma unroll
            for (int i = 0; i < 2; i++)
#pragma unroll
                for (int j = 0; j < 2; j++) {
                    pa[i * 2 + j] = *(const float4*)&Ap[(size_t)(r0 + i * 64) * K + c4 + j * 16];
                    pb[i * 2 + j] = *(const float4*)&Wp[(size_t)(r0 + i * 64) * K + c4 + j * 16];
                }
        }

#pragma unroll
        for (int ks = 0; ks < 2; ks++) {
            int kp0 = ks * 8;
            uint32_t afh[4][4], afl[4][4], bfh[4][2], bfl[4][2];
#pragma unroll
            for (int mi = 0; mi < 4; mi++) {
                int m0 = wm * 64 + mi * 16;
                afh[mi][0] = Ah[kp0 + tig][m0 + g];
                afh[mi][1] = Ah[kp0 + tig][m0 + g + 8];
                afh[mi][2] = Ah[kp0 + tig + 4][m0 + g];
                afh[mi][3] = Ah[kp0 + tig + 4][m0 + g + 8];
                afl[mi][0] = Al[kp0 + tig][m0 + g];
                afl[mi][1] = Al[kp0 + tig][m0 + g + 8];
                afl[mi][2] = Al[kp0 + tig + 4][m0 + g];
                afl[mi][3] = Al[kp0 + tig + 4][m0 + g + 8];
            }
#pragma unroll
            for (int ni = 0; ni < 4; ni++) {
                int n0 = wn * 32 + ni * 8;
                bfh[ni][0] = Bh[kp0 + tig][n0 + g];
                bfh[ni][1] = Bh[kp0 + tig + 4][n0 + g];
                bfl[ni][0] = Bl[kp0 + tig][n0 + g];
                bfl[ni][1] = Bl[kp0 + tig + 4][n0 + g];
            }
#pragma unroll
            for (int mi = 0; mi < 4; mi++)
#pragma unroll
                for (int ni = 0; ni < 4; ni++)
                    mma3(acc[mi][ni], afh[mi], afl[mi], bfh[ni], bfl[ni]);
        }
        __syncthreads();
    }

    // epilogue
#pragma unroll
    for (int mi = 0; mi < 4; mi++) {
#pragma unroll
        for (int ni = 0; ni < 4; ni++) {
#pragma unroll
            for (int c = 0; c < 4; c++) {
                int row = bm + wm * 64 + mi * 16 + g + (c >= 2 ? 8 : 0);
                int col = bn + wn * 32 + ni * 8 + tig * 2 + (c & 1);
                float val = acc[mi][ni][c] + bias[col];
                if (MODE == 0) {
                    int b = row / S_, s = row % S_;
                    if (col < NH_ * HD_) {
                        int h = col / HD_, d = col % HD_;
                        g_q[(((size_t)(b * NH_ + h)) * S_ + s) * HD_ + d] = val * g_qscale[d];
                    } else if (col < NH_ * HD_ + NKV_ * HD_) {
                        int cc = col - NH_ * HD_;
                        int h = cc / HD_, d = cc % HD_;
                        g_k[(((size_t)(b * NKV_ + h)) * S_ + s) * HD_ + d] = val;
                    } else {
                        int cc = col - NH_ * HD_ - NKV_ * HD_;
                        int h = cc / HD_, d = cc % HD_;
                        g_v[(((size_t)(b * NKV_ + h)) * S_ + s) * HD_ + d] = val;
                    }
                } else {
                    C[(size_t)row * N + col] = val;
                }
            }
        }
    }
}

// ---------------- causal flash attention w/ bf16x2 3-term MMA, BR=BC=64 ----------------
#define BR_ 64
#define BC_ 64

struct AttnSmem {
    uint32_t Qh[40][72], Ql[40][72];   // [d-pair][q-row]
    uint32_t Kh[40][72], Kl[40][72];   // [d-pair][kv-col]
    uint32_t Vh[32][88], Vl[32][88];   // [kv-pair][d]
    float Ps[BR_][68];                 // S then P (f32)
    float row_scale[BR_];
};

__global__ __launch_bounds__(256) void attn_kernel() {
    extern __shared__ char smem_raw[];
    AttnSmem& sm = *reinterpret_cast<AttnSmem*>(smem_raw);

    int tid = threadIdx.x;
    int lane = tid & 31, wid = tid >> 5;
    int g = lane >> 2, tig = lane & 3;
    int wm = wid >> 1, wn = wid & 1;   // wm 0..3 (16 rows each), wn 0..1
    int qt = blockIdx.x, bh = blockIdx.y;
    int b = bh / NH_, h = bh % NH_;
    int kvh = h / GQA_G_;
    int q0 = qt * BR_;

    const float* qptr  = g_q + ((size_t)bh * S_ + q0) * HD_;
    const float* kbase = g_k + ((size_t)(b * NKV_ + kvh)) * S_ * HD_;
    const float* vbase = g_v + ((size_t)(b * NKV_ + kvh)) * S_ * HD_;

    // load + split Q tile once: Qh/Ql[kp][row]
    for (int i = tid; i < BR_ * (HD_ / 4); i += 256) {
        int r = i / (HD_ / 4);
        int cc = (i % (HD_ / 4)) * 4;
        float4 qv = *(const float4*)&qptr[(size_t)r * HD_ + cc];
        int kp = cc >> 1;
        split_pack(qv.x, qv.y, sm.Qh[kp][r],     sm.Ql[kp][r]);
        split_pack(qv.z, qv.w, sm.Qh[kp + 1][r], sm.Ql[kp + 1][r]);
    }

    float accO[5][4];
#pragma unroll
    for (int ni = 0; ni < 5; ni++)
#pragma unroll
        for (int c = 0; c < 4; c++) accO[ni][c] = 0.0f;

    int srow = tid >> 2, quad = tid & 3;
    int qrow = q0 + srow;
    float mrow = -3.0e38f, lrow = 0.0f;

    for (int kt = 0; kt <= qt; kt++) {
        int k0 = kt * BC_;
        __syncthreads();   // prev-iter consumers done (covers Q fill on iter 0)

        const float* kp_ = kbase + (size_t)k0 * HD_;
        const float* vp_ = vbase + (size_t)k0 * HD_;
        for (int i = tid; i < BC_ * (HD_ / 4); i += 256) {
            int r = i / (HD_ / 4);               // kv row
            int cc = (i % (HD_ / 4)) * 4;        // d
            float4 kv = *(const float4*)&kp_[(size_t)r * HD_ + cc];
            int kp = cc >> 1;
            split_pack(kv.x, kv.y, sm.Kh[kp][r],     sm.Kl[kp][r]);
            split_pack(kv.z, kv.w, sm.Kh[kp + 1][r], sm.Kl[kp + 1][r]);

            float4 vv = *(const float4*)&vp_[(size_t)r * HD_ + cc];
            int vkp = r >> 1, par = r & 1;
            uint16_t* vh16 = (uint16_t*)&sm.Vh[vkp][0];
            uint16_t* vl16 = (uint16_t*)&sm.Vl[vkp][0];
            float xs[4] = {vv.x, vv.y, vv.z, vv.w};
#pragma unroll
            for (int j = 0; j < 4; j++) {
                unsigned short hb = bf16b(xs[j]);
                float hf = __uint_as_float((uint32_t)hb << 16);
                vh16[(cc + j) * 2 + par] = hb;
                vl16[(cc + j) * 2 + par] = bf16b(xs[j] - hf);
            }
        }
        __syncthreads();

        // ---- S = Q K^T; warp tile 16x32 at (wm*16, wn*32); 5 k-chunks of 16 d ----
        float sfrag[4][4];
#pragma unroll
        for (int ni = 0; ni < 4; ni++)
#pragma unroll
            for (int c = 0; c < 4; c++) sfrag[ni][c] = 0.0f;

#pragma unroll
        for (int ks = 0; ks < 5; ks++) {
            int kp0 = ks * 8;
            int m0 = wm * 16;
            uint32_t ah[4], al[4];
            ah[0] = sm.Qh[kp0 + tig][m0 + g];       al[0] = sm.Ql[kp0 + tig][m0 + g];
            ah[1] = sm.Qh[kp0 + tig][m0 + g + 8];   al[1] = sm.Ql[kp0 + tig][m0 + g + 8];
            ah[2] = sm.Qh[kp0 + tig + 4][m0 + g];   al[2] = sm.Ql[kp0 + tig + 4][m0 + g];
            ah[3] = sm.Qh[kp0 + tig + 4][m0 + g + 8]; al[3] = sm.Ql[kp0 + tig + 4][m0 + g + 8];
#pragma unroll
            for (int ni = 0; ni < 4; ni++) {
                int n0 = wn * 32 + ni * 8;
                uint32_t bh2[2], bl2[2];
                bh2[0] = sm.Kh[kp0 + tig][n0 + g];     bl2[0] = sm.Kl[kp0 + tig][n0 + g];
                bh2[1] = sm.Kh[kp0 + tig + 4][n0 + g]; bl2[1] = sm.Kl[kp0 + tig + 4][n0 + g];
                mma3(sfrag[ni], ah, al, bh2, bl2);
            }
        }
        // store S
#pragma unroll
        for (int ni = 0; ni < 4; ni++) {
            int n0 = wn * 32 + ni * 8 + tig * 2;
            sm.Ps[wm * 16 + g][n0]     = sfrag[ni][0];
            sm.Ps[wm * 16 + g][n0 + 1] = sfrag[ni][1];
            sm.Ps[wm * 16 + g + 8][n0]     = sfrag[ni][2];
            sm.Ps[wm * 16 + g + 8][n0 + 1] = sfrag[ni][3];
        }
        __syncthreads();

        // ---- online softmax (SIMT): 4 threads per row ----
        {
            float sv[16];
            float mx = -3.0e38f;
            bool diag = (kt == qt);
#pragma unroll
            for (int c = 0; c < 16; c++) {
                int col = quad * 16 + c;
                float x = sm.Ps[srow][col];
                if (diag && (k0 + col) > qrow) x = -3.0e38f;
                sv[c] = x;
                mx = fmaxf(mx, x);
            }
            mx = fmaxf(mx, __shfl_xor_sync(0xffffffffu, mx, 1));
            mx = fmaxf(mx, __shfl_xor_sync(0xffffffffu, mx, 2));
            float mnew = fmaxf(mrow, mx);
            float alpha = __expf(mrow - mnew);
            float psum = 0.0f;
#pragma unroll
            for (int c = 0; c < 16; c++) {
                float p = __expf(sv[c] - mnew);
                sm.Ps[srow][quad * 16 + c] = p;
                psum += p;
            }
            psum += __shfl_xor_sync(0xffffffffu, psum, 1);
            psum += __shfl_xor_sync(0xffffffffu, psum, 2);
            lrow = lrow * alpha + psum;
            mrow = mnew;
            if (quad == 0) sm.row_scale[srow] = alpha;
        }
        __syncthreads();

        // ---- rescale + O += P V; warp tile 16x40 at (wm*16, wn*40); 4 k-chunks of 16 kv ----
        {
            float al0 = sm.row_scale[wm * 16 + g];
            float al1 = sm.row_scale[wm * 16 + g + 8];
#pragma unroll
            for (int ni = 0; ni < 5; ni++) {
                accO[ni][0] *= al0; accO[ni][1] *= al0;
                accO[ni][2] *= al1; accO[ni][3] *= al1;
            }
#pragma unroll
            for (int ks = 0; ks < 4; ks++) {
                int kp0 = ks * 8;
                int m0 = wm * 16;
                int kv0 = ks * 16 + tig * 2;
                uint32_t ah[4], al[4];
                split_pack(sm.Ps[m0 + g][kv0],         sm.Ps[m0 + g][kv0 + 1],         ah[0], al[0]);
                split_pack(sm.Ps[m0 + g + 8][kv0],     sm.Ps[m0 + g + 8][kv0 + 1],     ah[1], al[1]);
                split_pack(sm.Ps[m0 + g][kv0 + 8],     sm.Ps[m0 + g][kv0 + 9],         ah[2], al[2]);
                split_pack(sm.Ps[m0 + g + 8][kv0 + 8], sm.Ps[m0 + g + 8][kv0 + 9],     ah[3], al[3]);
#pragma unroll
                for (int ni = 0; ni < 5; ni++) {
                    int n0 = wn * 40 + ni * 8;
                    uint32_t bh2[2], bl2[2];
                    bh2[0] = sm.Vh[kp0 + tig][n0 + g];     bl2[0] = sm.Vl[kp0 + tig][n0 + g];
                    bh2[1] = sm.Vh[kp0 + tig + 4][n0 + g]; bl2[1] = sm.Vl[kp0 + tig + 4][n0 + g];
                    mma3(accO[ni], ah, al, bh2, bl2);
                }
            }
        }
    }

    // final normalization
    __syncthreads();
    if (quad == 0) sm.row_scale[srow] = 1.0f / lrow;
    __syncthreads();
    float l0 = sm.row_scale[wm * 16 + g];
    float l1 = sm.row_scale[wm * 16 + g + 8];
#pragma unroll
    for (int ni = 0; ni < 5; ni++) {
        int cout = wn * 40 + ni * 8 + tig * 2;
        int rr0 = q0 + wm * 16 + g;
        int rr1 = rr0 + 8;
        float* o0 = g_o + ((size_t)(b * S_) + rr0) * HID_ + h * HD_ + cout;
        float* o1 = g_o + ((size_t)(b * S_) + rr1) * HID_ + h * HD_ + cout;
        o0[0] = accO[ni][0] * l0; o0[1] = accO[ni][1] * l0;
        o1[0] = accO[ni][2] * l1; o1[1] = accO[ni][3] * l1;
    }
}

// ---------------- launch ----------------
extern "C" void kernel_launch(void* const* d_in, const int* in_sizes, int n_in,
                              void* d_out, int out_size) {
    const float* hs      = (const float*)d_in[0];
    const float* scaling = (const float*)d_in[2];
    const float* qkv_w   = (const float*)d_in[3];
    const float* qkv_b   = (const float*)d_in[4];
    const float* o_w     = (const float*)d_in[5];
    const float* o_b     = (const float*)d_in[6];
    float* out = (float*)d_out;

    const int attn_smem = (int)sizeof(AttnSmem);
    cudaFuncSetAttribute(attn_kernel, cudaFuncAttributeMaxDynamicSharedMemorySize, attn_smem);

    qscale_kernel<<<1, 128>>>(scaling);

    dim3 g1(QKV_DIM_ / 128, M_TOT_ / 128);
    gemm_tc<0><<<g1, 256>>>(hs, qkv_w, qkv_b, nullptr, QKV_DIM_, HID_);

    dim3 ga(S_ / BR_, B_ * NH_);
    attn_kernel<<<ga, 256, attn_smem>>>();

    dim3 g3(HID_ / 128, M_TOT_ / 128);
    gemm_tc<1><<<g3, 256>>>(nullptr, o_w, o_b, out, HID_, HID_);
}